// round 12
// baseline (speedup 1.0000x reference)
#include <cuda_runtime.h>
#include <cuda_bf16.h>
#include <cstdint>

// CTC forward negative log-likelihood (keras ctc_batch_cost semantics).
// B=128, T=1024, V=512, L=128, S=2L+1=257, blank=V-1.
//
// Round-12 design ("composed 2-step update, race-free prefetch"):
//  - 1 CTA/batch (grid=128), 288 threads, thread s=tid owns state s
//    (conflict-free alpha LDS/STS), 4-entry NEGV front pad, ONE __syncthreads
//    per 2 time steps, cp.async 8-deep row ring (tid<128, 2 rows/group).
//  - Two DP steps composed algebraically into ONE 5-term weighted logsumexp:
//      alpha_{t+2}[s] = m + lg2( (sum_j W_j * 2^(alpha_t[s-j]-m)) * q_s )
//    with LINEAR path weights (FMA only):
//      W0 = p_s
//      W1 = p_s + p_m1
//      W2 = cs_s ? (p_s + p_m1 + p_m2) : p_m1
//      W3 = (cs_m1 ? p_m1 : 0) + (cs_s ? p_m2 : 0)
//      W4 = (cs_s && cs_m2) ? p_m2 : 0
//    (p_x = row_t[class(x)] + EPS, q_s = row_{t+1}[class(s)] + EPS).
//    Exactly equivalent to two chained logaddexp2 steps.
//  - RACE FIX vs R11: the P/Q prefetch for the NEXT iteration now happens
//    AFTER cp_wait<2> + __syncthreads, where rows t+2/t+3 are provably
//    complete and visible to all threads. (Previously it read rows that could
//    still be in flight -> nondeterministic corruption, rel_err ~9e-4.)
//  - Compute phase touches only registers + alpha shared; the barrier's
//    pre-region carries no scattered LDS.

#define NEGV (-1e30f)
#define EPSV (1e-7f)
#define LN2F (0.6931471805599453f)

constexpr int Bc = 128;
constexpr int Tc = 1024;
constexpr int Vc = 512;
constexpr int Lc = 128;
constexpr int Sc = 257;     // 2L+1
constexpr int D  = 8;       // ring stages (16KB)
constexpr int NT = 288;     // 9 warps

__device__ __forceinline__ float ex2f(float x) {
    float r; asm("ex2.approx.f32 %0, %1;" : "=f"(r) : "f"(x)); return r;
}
__device__ __forceinline__ float lg2f(float x) {
    float r; asm("lg2.approx.f32 %0, %1;" : "=f"(r) : "f"(x)); return r;
}
__device__ __forceinline__ void cp_async16(uint32_t saddr, const void* gptr) {
    asm volatile("cp.async.cg.shared.global [%0], [%1], 16;" :: "r"(saddr), "l"(gptr));
}
__device__ __forceinline__ void cp_commit() {
    asm volatile("cp.async.commit_group;");
}
template<int N>
__device__ __forceinline__ void cp_wait() {
    asm volatile("cp.async.wait_group %0;" :: "n"(N));
}

__global__ __launch_bounds__(NT, 1)
void ctc_forward_kernel(const int*   __restrict__ labels,     // [B, L]
                        const int*   __restrict__ lab_len,    // [B, 1]
                        const float* __restrict__ Y,          // [B, T, V]
                        const int*   __restrict__ in_len,     // [B, 1]
                        float*       __restrict__ out)        // [B, 1]
{
    __shared__ __align__(16) float rows[D][Vc];   // staged probability rows
    __shared__ float As[2][Sc + 8];               // alpha: 4 front-pad + 257 + tail
    __shared__ int   lab_sh[Lc];

    const int b   = blockIdx.x;
    const int tid = threadIdx.x;

    if (tid < Lc) lab_sh[tid] = labels[b * Lc + tid];
    const int len = in_len[b];

    const bool active = (tid <= 256);
    const int  s      = tid;

    if (tid < 4) { As[0][tid] = NEGV; As[1][tid] = NEGV; }
    if (active) As[0][4 + s] = (s == 0) ? 0.0f : NEGV;    // log2 domain

    const float* __restrict__ Yb = Y + (size_t)b * Tc * Vc;
    const bool producer = (tid < 128);
    const uint32_t rows_sb = (uint32_t)__cvta_generic_to_shared(&rows[0][0]);

    // ---- prologue: stage rows 0..D-1 (2 rows per commit group) ----
    if (producer) {
        #pragma unroll
        for (int g = 0; g < D / 2; g++) {
            #pragma unroll
            for (int r = 0; r < 2; r++) {
                const int j  = 2 * g + r;
                const int tr = (j < len) ? j : (len > 0 ? len - 1 : 0);
                cp_async16(rows_sb + (uint32_t)j * 2048u + (uint32_t)tid * 16u,
                           Yb + (size_t)tr * Vc + tid * 4);
            }
            cp_commit();
        }
        cp_wait<2>();                 // rows 0..3 complete
    }
    __syncthreads();                  // labels, alpha0, rows 0..3 visible

    // ---- per-thread constants (classes + skip flags for s, s-1, s-2) ----
    const int  blank = Vc - 1;
    const bool sOdd  = (s & 1) != 0;
    int  cls_s  = blank, cls_m1 = blank, cls_m2 = blank;
    bool cs_s = false, cs_m1 = false, cs_m2 = false;
    if (active) {
        if (sOdd) {
            cls_s  = lab_sh[(s - 1) >> 1];
            cls_m2 = (s >= 3) ? lab_sh[(s - 3) >> 1] : blank;
            cs_s   = (s >= 3) && (cls_s != cls_m2) && (cls_s != blank);
            cs_m2  = (s >= 5) && (lab_sh[(s - 3) >> 1] != lab_sh[(s - 5) >> 1])
                              && (cls_m2 != blank);
        } else {
            cls_m1 = (s >= 2) ? lab_sh[(s - 2) >> 1] : blank;
            cs_m1  = (s >= 4) && (lab_sh[(s - 2) >> 1] != lab_sh[(s - 4) >> 1])
                              && (cls_m1 != blank);
        }
    }
    const bool pm3 = cs_m1 || cs_s;       // W3 > 0 ?
    const bool pm4 = cs_s && cs_m2;       // W4 > 0 ?

    // ---- prefetch p/q for iteration t=0 (rows 0,1 complete) ----
    float P0 = EPSV, P1 = EPSV, P2 = EPSV, Qs = EPSV;
    if (active) {
        P0 = rows[0][cls_s]  + EPSV;
        P1 = rows[0][cls_m1] + EPSV;
        P2 = rows[0][cls_m2] + EPSV;
        Qs = rows[1][cls_s]  + EPSV;
    }

    // ---- main recursion: 2 composed steps per barrier ----
    int rd = 0;
    int t  = 0;
    for (; t + 1 < len; t += 2) {
        if (active) {
            // linear path weights (FMA/ALU only)
            const float W0 = P0;
            const float W1 = P0 + P1;
            const float W2 = cs_s ? (W1 + P2) : P1;
            const float W3 = (cs_m1 ? P1 : 0.0f) + (cs_s ? P2 : 0.0f);
            const float W4 = pm4 ? P2 : 0.0f;

            const float* __restrict__ A = &As[rd][4];   // A[i] = alpha_t[i]
            const float A0 = A[s];
            const float A1 = A[s - 1];
            const float A2 = A[s - 2];
            const float A3 = pm3 ? A[s - 3] : NEGV;     // mask zero-weight terms
            const float A4 = pm4 ? A[s - 4] : NEGV;

            const float m = fmaxf(fmaxf(fmaxf(A0, A1), fmaxf(A2, A3)), A4);
            const float x0 = ex2f(A0 - m);
            const float x1 = ex2f(A1 - m);
            const float x2 = ex2f(A2 - m);
            const float x3 = ex2f(A3 - m);
            const float x4 = ex2f(A4 - m);
            const float sum = (W0 * x0 + W1 * x1) + (W2 * x2 + (W3 * x3 + W4 * x4));
            As[rd ^ 1][4 + s] = m + lg2f(sum * Qs);
        }

        if (producer) cp_wait<2>();   // rows t+2..t+5 complete (their copies)
        __syncthreads();              // publish alpha_{t+2}; completed rows
                                      // visible to ALL threads; slots t,t+1 retired
        if (producer && (t + D) < len) {
            #pragma unroll
            for (int r = 0; r < 2; r++) {
                const int j  = t + D + r;
                const int tr = (j < len) ? j : (len - 1);
                cp_async16(rows_sb + (uint32_t)(j & (D - 1)) * 2048u + (uint32_t)tid * 16u,
                           Yb + (size_t)tr * Vc + tid * 4);
            }
            cp_commit();
        }

        // RACE-FREE prefetch for iteration t+2: rows t+2, t+3 are complete
        // (cp_wait<2> left at most groups (t+4,t+5),(t+6,t+7) pending) and
        // visible (barrier above). Overlaps the next iteration's compute head.
        if (active && (t + 2) + 1 < len) {
            const float* __restrict__ r0n = rows[(t + 2) & (D - 1)];
            const float* __restrict__ r1n = rows[(t + 3) & (D - 1)];
            P0 = r0n[cls_s]  + EPSV;
            P1 = r0n[cls_m1] + EPSV;
            P2 = r0n[cls_m2] + EPSV;
            Qs = r1n[cls_s]  + EPSV;
        } else if (active && (t + 2) < len) {
            // odd tail prep: only row t+2 needed
            const float* __restrict__ r0n = rows[(t + 2) & (D - 1)];
            P0 = r0n[cls_s] + EPSV;
        }
        rd ^= 1;
    }

    // ---- odd tail: one single step (len odd) ----
    if (t < len) {
        if (active) {
            const float* __restrict__ A = &As[rd][4];
            const float A0 = A[s];
            const float A1 = A[s - 1];
            const float A2 = cs_s ? A[s - 2] : NEGV;
            const float m  = fmaxf(fmaxf(A0, A1), A2);
            const float sum = ex2f(A0 - m) + ex2f(A1 - m) + ex2f(A2 - m);
            As[rd ^ 1][4 + s] = m + lg2f(sum * P0);   // P0 = p_s at row t
        }
        __syncthreads();
        rd ^= 1;
    }

    // ---- final: loss = -ln2 * logaddexp2(alpha[2*lab], alpha[2*lab-1]) ----
    if (tid == 0) {
        const int   ll = lab_len[b];
        const float aL = As[rd][4 + 2 * ll];
        const float aP = As[rd][4 + 2 * ll - 1];
        const float mm = fmaxf(aL, aP);
        const float ql = fminf(aL, aP);
        out[b] = -LN2F * (mm + lg2f(1.0f + ex2f(ql - mm)));
    }
}

extern "C" void kernel_launch(void* const* d_in, const int* in_sizes, int n_in,
                              void* d_out, int out_size) {
    const int*   labels  = (const int*)d_in[0];   // true_labels [B, L]
    const int*   lab_len = (const int*)d_in[1];   // true_lengths [B, 1]
    const float* Y       = (const float*)d_in[2]; // predicted_labels [B, T, V]
    const int*   in_len  = (const int*)d_in[3];   // predicted_lengths [B, 1]
    float*       out     = (float*)d_out;         // [B, 1]

    ctc_forward_kernel<<<Bc, NT>>>(labels, lab_len, Y, in_len, out);
}

// round 13
// speedup vs baseline: 1.0330x; 1.0330x over previous
#include <cuda_runtime.h>
#include <cuda_bf16.h>
#include <cstdint>

// CTC forward negative log-likelihood (keras ctc_batch_cost semantics).
// B=128, T=1024, V=512, L=128, S=2L+1=257, blank=V-1.
//
// Round-13 design ("composed 2-step update, deep-wait race-free prefetch"):
//  - 1 CTA/batch (grid=128), 288 threads, thread s=tid owns state s
//    (conflict-free alpha LDS/STS), 4-entry NEGV front pad, ONE __syncthreads
//    per 2 time steps, cp.async 8-deep row ring (tid<128, 2 rows/group).
//  - Two DP steps composed algebraically into ONE 5-term weighted logsumexp:
//      alpha_{t+2}[s] = m + lg2( (sum_j W_j * 2^(alpha_t[s-j]-m)) * q_s )
//    with LINEAR path weights (FMA only):
//      W0 = p_s ; W1 = p_s + p_m1 ; W2 = cs_s ? (W1 + p_m2) : p_m1
//      W3 = (cs_m1 ? p_m1 : 0) + (cs_s ? p_m2 : 0) ; W4 = (cs_s&&cs_m2)?p_m2:0
//    Exactly equivalent to two chained logaddexp2 steps.
//  - RACE-FREE FAST PREFETCH (the R11-speed / R12-correctness synthesis):
//    cp.async.wait_group<1> before each barrier => at the barrier opening
//    iteration t, every group except the newest is complete, i.e. rows t+2 and
//    t+3 are complete AND visible. Therefore the P/Q prefetch for iteration
//    t+2 runs inside iteration t's COMPUTE phase (off the post-barrier serial
//    path) with no possibility of reading in-flight data.
//    Invariant trace: prologue issues (0,1),(2,3),(4,5),(6,7), wait<1> -> rows
//    0..5 done. Iter t: issue (t+8,t+9) happens after the barrier; the wait<1>
//    closing iter t completes (t+4,t+5). Induction: during iter t the newest
//    group is (t+6,t+7); all rows <= t+5 complete; prefetch touches t+2,t+3.

#define NEGV (-1e30f)
#define EPSV (1e-7f)
#define LN2F (0.6931471805599453f)

constexpr int Bc = 128;
constexpr int Tc = 1024;
constexpr int Vc = 512;
constexpr int Lc = 128;
constexpr int Sc = 257;     // 2L+1
constexpr int D  = 8;       // ring stages (16KB)
constexpr int NT = 288;     // 9 warps

__device__ __forceinline__ float ex2f(float x) {
    float r; asm("ex2.approx.f32 %0, %1;" : "=f"(r) : "f"(x)); return r;
}
__device__ __forceinline__ float lg2f(float x) {
    float r; asm("lg2.approx.f32 %0, %1;" : "=f"(r) : "f"(x)); return r;
}
__device__ __forceinline__ void cp_async16(uint32_t saddr, const void* gptr) {
    asm volatile("cp.async.cg.shared.global [%0], [%1], 16;" :: "r"(saddr), "l"(gptr));
}
__device__ __forceinline__ void cp_commit() {
    asm volatile("cp.async.commit_group;");
}
template<int N>
__device__ __forceinline__ void cp_wait() {
    asm volatile("cp.async.wait_group %0;" :: "n"(N));
}

__global__ __launch_bounds__(NT, 1)
void ctc_forward_kernel(const int*   __restrict__ labels,     // [B, L]
                        const int*   __restrict__ lab_len,    // [B, 1]
                        const float* __restrict__ Y,          // [B, T, V]
                        const int*   __restrict__ in_len,     // [B, 1]
                        float*       __restrict__ out)        // [B, 1]
{
    __shared__ __align__(16) float rows[D][Vc];   // staged probability rows
    __shared__ float As[2][Sc + 8];               // alpha: 4 front-pad + 257 + tail
    __shared__ int   lab_sh[Lc];

    const int b   = blockIdx.x;
    const int tid = threadIdx.x;

    if (tid < Lc) lab_sh[tid] = labels[b * Lc + tid];
    const int len = in_len[b];

    const bool active = (tid <= 256);
    const int  s      = tid;

    if (tid < 4) { As[0][tid] = NEGV; As[1][tid] = NEGV; }
    if (active) As[0][4 + s] = (s == 0) ? 0.0f : NEGV;    // log2 domain

    const float* __restrict__ Yb = Y + (size_t)b * Tc * Vc;
    const bool producer = (tid < 128);
    const uint32_t rows_sb = (uint32_t)__cvta_generic_to_shared(&rows[0][0]);

    // ---- prologue: stage rows 0..D-1 (2 rows per commit group) ----
    if (producer) {
        #pragma unroll
        for (int g = 0; g < D / 2; g++) {
            #pragma unroll
            for (int r = 0; r < 2; r++) {
                const int j  = 2 * g + r;
                const int tr = (j < len) ? j : (len > 0 ? len - 1 : 0);
                cp_async16(rows_sb + (uint32_t)j * 2048u + (uint32_t)tid * 16u,
                           Yb + (size_t)tr * Vc + tid * 4);
            }
            cp_commit();
        }
        cp_wait<1>();                 // rows 0..5 complete
    }
    __syncthreads();                  // labels, alpha0, rows 0..5 visible

    // ---- per-thread constants (classes + skip flags for s, s-1, s-2) ----
    const int  blank = Vc - 1;
    const bool sOdd  = (s & 1) != 0;
    int  cls_s  = blank, cls_m1 = blank, cls_m2 = blank;
    bool cs_s = false, cs_m1 = false, cs_m2 = false;
    if (active) {
        if (sOdd) {
            cls_s  = lab_sh[(s - 1) >> 1];
            cls_m2 = (s >= 3) ? lab_sh[(s - 3) >> 1] : blank;
            cs_s   = (s >= 3) && (cls_s != cls_m2) && (cls_s != blank);
            cs_m2  = (s >= 5) && (lab_sh[(s - 3) >> 1] != lab_sh[(s - 5) >> 1])
                              && (cls_m2 != blank);
        } else {
            cls_m1 = (s >= 2) ? lab_sh[(s - 2) >> 1] : blank;
            cs_m1  = (s >= 4) && (lab_sh[(s - 2) >> 1] != lab_sh[(s - 4) >> 1])
                              && (cls_m1 != blank);
        }
    }
    const bool pm3 = cs_m1 || cs_s;       // W3 > 0 ?
    const bool pm4 = cs_s && cs_m2;       // W4 > 0 ?

    // ---- prefetch p/q for iteration t=0 (rows 0,1 complete) ----
    float P0 = EPSV, P1 = EPSV, P2 = EPSV, Qs = EPSV;
    if (active) {
        P0 = rows[0][cls_s]  + EPSV;
        P1 = rows[0][cls_m1] + EPSV;
        P2 = rows[0][cls_m2] + EPSV;
        Qs = rows[1][cls_s]  + EPSV;
    }

    // ---- main recursion: 2 composed steps per barrier ----
    int rd = 0;
    int t  = 0;
    for (; t + 1 < len; t += 2) {
        if (active) {
            // linear path weights (FMA/ALU only)
            const float W0 = P0;
            const float W1 = P0 + P1;
            const float W2 = cs_s ? (W1 + P2) : P1;
            const float W3 = (cs_m1 ? P1 : 0.0f) + (cs_s ? P2 : 0.0f);
            const float W4 = pm4 ? P2 : 0.0f;

            const float* __restrict__ A = &As[rd][4];   // A[i] = alpha_t[i]
            const float A0 = A[s];
            const float A1 = A[s - 1];
            const float A2 = A[s - 2];
            const float A3 = pm3 ? A[s - 3] : NEGV;     // mask zero-weight terms
            const float A4 = pm4 ? A[s - 4] : NEGV;

            const float m = fmaxf(fmaxf(fmaxf(A0, A1), fmaxf(A2, A3)), A4);
            const float x0 = ex2f(A0 - m);
            const float x1 = ex2f(A1 - m);
            const float x2 = ex2f(A2 - m);
            const float x3 = ex2f(A3 - m);
            const float x4 = ex2f(A4 - m);
            const float sum = (W0 * x0 + W1 * x1) + (W2 * x2 + (W3 * x3 + W4 * x4));
            As[rd ^ 1][4 + s] = m + lg2f(sum * Qs);

            // SAFE pre-barrier prefetch for iteration t+2: rows t+2, t+3 were
            // complete before this iteration's opening barrier (wait<1>
            // invariant) and are visible. Overlaps the barrier wait.
            if (t + 3 < len) {
                const float* __restrict__ r0n = rows[(t + 2) & (D - 1)];
                const float* __restrict__ r1n = rows[(t + 3) & (D - 1)];
                P0 = r0n[cls_s]  + EPSV;
                P1 = r0n[cls_m1] + EPSV;
                P2 = r0n[cls_m2] + EPSV;
                Qs = r1n[cls_s]  + EPSV;
            } else if (t + 2 < len) {
                P0 = rows[(t + 2) & (D - 1)][cls_s] + EPSV;   // odd tail
            }
        }

        if (producer) cp_wait<1>();   // all groups except newest complete
        __syncthreads();              // publish alpha_{t+2}; rows visible; slots retired
        if (producer && (t + D) < len) {
            #pragma unroll
            for (int r = 0; r < 2; r++) {
                const int j  = t + D + r;
                const int tr = (j < len) ? j : (len - 1);
                cp_async16(rows_sb + (uint32_t)(j & (D - 1)) * 2048u + (uint32_t)tid * 16u,
                           Yb + (size_t)tr * Vc + tid * 4);
            }
            cp_commit();
        }
        rd ^= 1;
    }

    // ---- odd tail: one single step (len odd) ----
    if (t < len) {
        if (active) {
            const float* __restrict__ A = &As[rd][4];
            const float A0 = A[s];
            const float A1 = A[s - 1];
            const float A2 = cs_s ? A[s - 2] : NEGV;
            const float m  = fmaxf(fmaxf(A0, A1), A2);
            const float sum = ex2f(A0 - m) + ex2f(A1 - m) + ex2f(A2 - m);
            As[rd ^ 1][4 + s] = m + lg2f(sum * P0);   // P0 = p_s at row t
        }
        __syncthreads();
        rd ^= 1;
    }

    // ---- final: loss = -ln2 * logaddexp2(alpha[2*lab], alpha[2*lab-1]) ----
    if (tid == 0) {
        const int   ll = lab_len[b];
        const float aL = As[rd][4 + 2 * ll];
        const float aP = As[rd][4 + 2 * ll - 1];
        const float mm = fmaxf(aL, aP);
        const float ql = fminf(aL, aP);
        out[b] = -LN2F * (mm + lg2f(1.0f + ex2f(ql - mm)));
    }
}

extern "C" void kernel_launch(void* const* d_in, const int* in_sizes, int n_in,
                              void* d_out, int out_size) {
    const int*   labels  = (const int*)d_in[0];   // true_labels [B, L]
    const int*   lab_len = (const int*)d_in[1];   // true_lengths [B, 1]
    const float* Y       = (const float*)d_in[2]; // predicted_labels [B, T, V]
    const int*   in_len  = (const int*)d_in[3];   // predicted_lengths [B, 1]
    float*       out     = (float*)d_out;         // [B, 1]

    ctc_forward_kernel<<<Bc, NT>>>(labels, lab_len, Y, in_len, out);
}

// round 14
// speedup vs baseline: 1.1469x; 1.1103x over previous
#include <cuda_runtime.h>
#include <cuda_bf16.h>
#include <cstdint>

// CTC forward negative log-likelihood (keras ctc_batch_cost semantics).
// B=128, T=1024, V=512, L=128, S=2L+1=257, blank=V-1.
//
// Round-14 design ("composed 2-step, deep ring + slack wait"):
//  - 1 CTA/batch (grid=128), 288 threads, thread s=tid owns state s
//    (conflict-free alpha LDS/STS), 4-entry NEGV front pad, ONE __syncthreads
//    per 2 time steps. cp.async row ring now D=16 (32KB, 8 groups in flight),
//    producers tid<128, 2 rows per commit group.
//  - Two DP steps composed algebraically into ONE 5-term weighted logsumexp:
//      alpha_{t+2}[s] = m + lg2( (sum_j W_j * 2^(alpha_t[s-j]-m)) * q_s )
//    LINEAR path weights (FMA only):
//      W0 = p_s ; W1 = p_s + p_m1 ; W2 = cs_s ? (W1 + p_m2) : p_m1
//      W3 = (cs_m1 ? p_m1 : 0) + (cs_s ? p_m2 : 0) ; W4 = (cs_s&&cs_m2)?p_m2:0
//    Exactly equivalent to two chained logaddexp2 steps.
//  - RACE-FREE NON-BLOCKING PREFETCH: wait_group<4> with 8 groups in flight.
//    The group holding rows (t+2,t+3) has 6 newer groups at the wait closing
//    iteration t-2, so wait<4> proves it complete; the barrier publishes it;
//    the P/Q prefetch for iteration t+2 runs inside iteration t's compute
//    phase (overlapping the barrier) with zero UB. The wait only requires
//    copies issued >=5 iterations (~1300+ cyc) earlier -> never blocks.
//    (R13 proved safety with wait<1> but blocked the producers; R11 had this
//    schedule but an unproven wait<2> at D=8 -> racy. D=16 gives both.)

#define NEGV (-1e30f)
#define EPSV (1e-7f)
#define LN2F (0.6931471805599453f)

constexpr int Bc = 128;
constexpr int Tc = 1024;
constexpr int Vc = 512;
constexpr int Lc = 128;
constexpr int Sc = 257;     // 2L+1
constexpr int D  = 16;      // ring stages (32KB)
constexpr int NT = 288;     // 9 warps

__device__ __forceinline__ float ex2f(float x) {
    float r; asm("ex2.approx.f32 %0, %1;" : "=f"(r) : "f"(x)); return r;
}
__device__ __forceinline__ float lg2f(float x) {
    float r; asm("lg2.approx.f32 %0, %1;" : "=f"(r) : "f"(x)); return r;
}
__device__ __forceinline__ void cp_async16(uint32_t saddr, const void* gptr) {
    asm volatile("cp.async.cg.shared.global [%0], [%1], 16;" :: "r"(saddr), "l"(gptr));
}
__device__ __forceinline__ void cp_commit() {
    asm volatile("cp.async.commit_group;");
}
template<int N>
__device__ __forceinline__ void cp_wait() {
    asm volatile("cp.async.wait_group %0;" :: "n"(N));
}

__global__ __launch_bounds__(NT, 1)
void ctc_forward_kernel(const int*   __restrict__ labels,     // [B, L]
                        const int*   __restrict__ lab_len,    // [B, 1]
                        const float* __restrict__ Y,          // [B, T, V]
                        const int*   __restrict__ in_len,     // [B, 1]
                        float*       __restrict__ out)        // [B, 1]
{
    __shared__ __align__(16) float rows[D][Vc];   // staged probability rows (32KB)
    __shared__ float As[2][Sc + 8];               // alpha: 4 front-pad + 257 + tail
    __shared__ int   lab_sh[Lc];

    const int b   = blockIdx.x;
    const int tid = threadIdx.x;

    if (tid < Lc) lab_sh[tid] = labels[b * Lc + tid];
    const int len = in_len[b];

    const bool active = (tid <= 256);
    const int  s      = tid;

    if (tid < 4) { As[0][tid] = NEGV; As[1][tid] = NEGV; }
    if (active) As[0][4 + s] = (s == 0) ? 0.0f : NEGV;    // log2 domain

    const float* __restrict__ Yb = Y + (size_t)b * Tc * Vc;
    const bool producer = (tid < 128);
    const uint32_t rows_sb = (uint32_t)__cvta_generic_to_shared(&rows[0][0]);

    // ---- prologue: stage rows 0..D-1 (2 rows per commit group, 8 groups) ----
    if (producer) {
        #pragma unroll
        for (int g = 0; g < D / 2; g++) {
            #pragma unroll
            for (int r = 0; r < 2; r++) {
                const int j  = 2 * g + r;
                const int tr = (j < len) ? j : (len > 0 ? len - 1 : 0);
                cp_async16(rows_sb + (uint32_t)j * 2048u + (uint32_t)tid * 16u,
                           Yb + (size_t)tr * Vc + tid * 4);
            }
            cp_commit();
        }
        cp_wait<4>();                 // groups 0..3 complete -> rows 0..7
    }
    __syncthreads();                  // labels, alpha0, rows 0..7 visible

    // ---- per-thread constants (classes + skip flags for s, s-1, s-2) ----
    const int  blank = Vc - 1;
    const bool sOdd  = (s & 1) != 0;
    int  cls_s  = blank, cls_m1 = blank, cls_m2 = blank;
    bool cs_s = false, cs_m1 = false, cs_m2 = false;
    if (active) {
        if (sOdd) {
            cls_s  = lab_sh[(s - 1) >> 1];
            cls_m2 = (s >= 3) ? lab_sh[(s - 3) >> 1] : blank;
            cs_s   = (s >= 3) && (cls_s != cls_m2) && (cls_s != blank);
            cs_m2  = (s >= 5) && (lab_sh[(s - 3) >> 1] != lab_sh[(s - 5) >> 1])
                              && (cls_m2 != blank);
        } else {
            cls_m1 = (s >= 2) ? lab_sh[(s - 2) >> 1] : blank;
            cs_m1  = (s >= 4) && (lab_sh[(s - 2) >> 1] != lab_sh[(s - 4) >> 1])
                              && (cls_m1 != blank);
        }
    }
    const bool pm3 = cs_m1 || cs_s;       // W3 > 0 ?
    const bool pm4 = cs_s && cs_m2;       // W4 > 0 ?

    // ---- prefetch p/q for iteration t=0 (rows 0,1 complete) ----
    float P0 = EPSV, P1 = EPSV, P2 = EPSV, Qs = EPSV;
    if (active) {
        P0 = rows[0][cls_s]  + EPSV;
        P1 = rows[0][cls_m1] + EPSV;
        P2 = rows[0][cls_m2] + EPSV;
        Qs = rows[1][cls_s]  + EPSV;
    }

    // ---- main recursion: 2 composed steps per barrier ----
    int rd = 0;
    int t  = 0;
    for (; t + 1 < len; t += 2) {
        if (active) {
            // linear path weights (FMA/ALU only)
            const float W0 = P0;
            const float W1 = P0 + P1;
            const float W2 = cs_s ? (W1 + P2) : P1;
            const float W3 = (cs_m1 ? P1 : 0.0f) + (cs_s ? P2 : 0.0f);
            const float W4 = pm4 ? P2 : 0.0f;

            const float* __restrict__ A = &As[rd][4];   // A[i] = alpha_t[i]
            const float A0 = A[s];
            const float A1 = A[s - 1];
            const float A2 = A[s - 2];
            const float A3 = pm3 ? A[s - 3] : NEGV;     // mask zero-weight terms
            const float A4 = pm4 ? A[s - 4] : NEGV;

            const float m = fmaxf(fmaxf(fmaxf(A0, A1), fmaxf(A2, A3)), A4);
            const float x0 = ex2f(A0 - m);
            const float x1 = ex2f(A1 - m);
            const float x2 = ex2f(A2 - m);
            const float x3 = ex2f(A3 - m);
            const float x4 = ex2f(A4 - m);
            const float sum = (W0 * x0 + W1 * x1) + (W2 * x2 + (W3 * x3 + W4 * x4));
            As[rd ^ 1][4 + s] = m + lg2f(sum * Qs);

            // Race-free prefetch for iteration t+2: rows t+2,t+3 were proven
            // complete by the wait<4> closing iteration t-2 (6 newer groups
            // in flight) and published by its barrier. Overlaps the barrier.
            if (t + 3 < len) {
                const float* __restrict__ r0n = rows[(t + 2) & (D - 1)];
                const float* __restrict__ r1n = rows[(t + 3) & (D - 1)];
                P0 = r0n[cls_s]  + EPSV;
                P1 = r0n[cls_m1] + EPSV;
                P2 = r0n[cls_m2] + EPSV;
                Qs = r1n[cls_s]  + EPSV;
            } else if (t + 2 < len) {
                P0 = rows[(t + 2) & (D - 1)][cls_s] + EPSV;   // odd tail
            }
        }

        if (producer) cp_wait<4>();   // all but newest 4 groups complete
        __syncthreads();              // publish alpha_{t+2}; rows visible; slots retired
        if (producer && (t + D) < len) {
            #pragma unroll
            for (int r = 0; r < 2; r++) {
                const int j  = t + D + r;
                const int tr = (j < len) ? j : (len - 1);
                cp_async16(rows_sb + (uint32_t)(j & (D - 1)) * 2048u + (uint32_t)tid * 16u,
                           Yb + (size_t)tr * Vc + tid * 4);
            }
            cp_commit();
        }
        rd ^= 1;
    }

    // ---- odd tail: one single step (len odd) ----
    if (t < len) {
        if (active) {
            const float* __restrict__ A = &As[rd][4];
            const float A0 = A[s];
            const float A1 = A[s - 1];
            const float A2 = cs_s ? A[s - 2] : NEGV;
            const float m  = fmaxf(fmaxf(A0, A1), A2);
            const float sum = ex2f(A0 - m) + ex2f(A1 - m) + ex2f(A2 - m);
            As[rd ^ 1][4 + s] = m + lg2f(sum * P0);   // P0 = p_s at row t
        }
        __syncthreads();
        rd ^= 1;
    }

    // ---- final: loss = -ln2 * logaddexp2(alpha[2*lab], alpha[2*lab-1]) ----
    if (tid == 0) {
        const int   ll = lab_len[b];
        const float aL = As[rd][4 + 2 * ll];
        const float aP = As[rd][4 + 2 * ll - 1];
        const float mm = fmaxf(aL, aP);
        const float ql = fminf(aL, aP);
        out[b] = -LN2F * (mm + lg2f(1.0f + ex2f(ql - mm)));
    }
}

extern "C" void kernel_launch(void* const* d_in, const int* in_sizes, int n_in,
                              void* d_out, int out_size) {
    const int*   labels  = (const int*)d_in[0];   // true_labels [B, L]
    const int*   lab_len = (const int*)d_in[1];   // true_lengths [B, 1]
    const float* Y       = (const float*)d_in[2]; // predicted_labels [B, T, V]
    const int*   in_len  = (const int*)d_in[3];   // predicted_lengths [B, 1]
    float*       out     = (float*)d_out;         // [B, 1]

    ctc_forward_kernel<<<Bc, NT>>>(labels, lab_len, Y, in_len, out);
}